// round 1
// baseline (speedup 1.0000x reference)
#include <cuda_runtime.h>
#include <cuda_bf16.h>
#include <math.h>

// Problem constants (fixed shapes from reference setup_inputs)
#define BATCH 8
#define SEQT  2048
#define DIM   1024
#define M_TOT (BATCH * SEQT)          // 16384
#define NCHUNK 32
#define CHUNK_LEN (SEQT / NCHUNK)      // 64

// ---------------- scratch (static device arrays: allocation-free) ----------------
__device__ float g_pa[(size_t)M_TOT * DIM];   // a = 1 - sigmoid(x Wz + bz)
__device__ float g_ph[(size_t)M_TOT * DIM];   // h_tilde = x Wh + bh ; later reused as y (swish(h))
__device__ float g_Ag[BATCH * NCHUNK * DIM];  // chunk aggregate A
__device__ float g_Bg[BATCH * NCHUNK * DIM];  // chunk aggregate B
__device__ float g_cr[BATCH * NCHUNK * DIM];  // chunk carry-in h

// ---------------- FFMA-only fast sigmoid (avoids MUFU throughput wall) -----------
// abs err < ~1e-5
__device__ __forceinline__ float sigmoid_fast(float x) {
    const float LOG2E = 1.4426950408889634f;
    float ax = fabsf(x);
    float t  = fminf(ax * LOG2E, 120.0f);       // exp(-ax) = 2^(-t), t >= 0
    float r  = -t;                               // [-120, 0]
    float n  = floorf(r);
    float f  = r - n;                            // [0,1)
    // 2^f, degree-6 Taylor in f*ln2
    float p = 1.5403530393381609e-4f;
    p = fmaf(p, f, 1.3333558146428443e-3f);
    p = fmaf(p, f, 9.618129107628477e-3f);
    p = fmaf(p, f, 5.550410866482158e-2f);
    p = fmaf(p, f, 2.402265069591007e-1f);
    p = fmaf(p, f, 6.931471805599453e-1f);
    p = fmaf(p, f, 1.0f);
    int ni = (int)n;                             // ni in [-121, 0]
    float scale = __int_as_float((ni + 127) << 23);
    float u = scale * p;                         // exp(-|x|) in (0, 1]
    // w = 1/(1+u): linear init + 3 Newton steps (all FFMA)
    float y  = 1.0f + u;                         // [1,2]
    float w  = fmaf(-0.5f, y, 1.4571f);
    float e;
    e = fmaf(-y, w, 1.0f); w = fmaf(w, e, w);
    e = fmaf(-y, w, 1.0f); w = fmaf(w, e, w);
    e = fmaf(-y, w, 1.0f); w = fmaf(w, e, w);
    return (x >= 0.0f) ? w : (1.0f - w);
}

// ---------------- fused dual GEMM: z-preact (-> a) and h_tilde -------------------
// C = x[M,K] * W[K,N], blockIdx.z selects {Wz -> g_pa (1-sigmoid)} or {Wh -> g_ph}
#define BM 128
#define BN 128
#define BK 16
#define TM 8
#define TN 8

__global__ __launch_bounds__(256) void gemm_fused_kernel(
    const float* __restrict__ X,
    const float* __restrict__ Wz, const float* __restrict__ bz,
    const float* __restrict__ Wh, const float* __restrict__ bh)
{
    const int z = blockIdx.z;
    const float* __restrict__ W    = (z == 0) ? Wz : Wh;
    const float* __restrict__ bias = (z == 0) ? bz : bh;
    float* __restrict__ out        = (z == 0) ? g_pa : g_ph;

    __shared__ float As[BK][BM + 4];   // padded: conflict-free transpose store, 16B-aligned rows
    __shared__ float Bs[BK][BN];

    const int tid  = threadIdx.x;
    const int row0 = blockIdx.y * BM;
    const int col0 = blockIdx.x * BN;

    // A-load mapping: 128 rows x 16 cols; 256 thr -> 2 passes of 64 rows, float4 per thread
    const int ar = tid >> 2;           // 0..63
    const int ac = (tid & 3) * 4;      // 0,4,8,12
    // B-load mapping: 16 rows x 128 cols; 2 passes of 8 rows
    const int br = tid >> 5;           // 0..7
    const int bc = (tid & 31) * 4;     // 0..124

    const int ty = tid >> 4;           // 0..15
    const int tx = tid & 15;           // 0..15

    float acc[TM][TN];
    #pragma unroll
    for (int i = 0; i < TM; i++)
        #pragma unroll
        for (int j = 0; j < TN; j++) acc[i][j] = 0.0f;

    for (int k0 = 0; k0 < DIM; k0 += BK) {
        #pragma unroll
        for (int p = 0; p < 2; p++) {
            const float4 v = *(const float4*)(X + (size_t)(row0 + ar + 64 * p) * DIM + (k0 + ac));
            As[ac + 0][ar + 64 * p] = v.x;
            As[ac + 1][ar + 64 * p] = v.y;
            As[ac + 2][ar + 64 * p] = v.z;
            As[ac + 3][ar + 64 * p] = v.w;
        }
        #pragma unroll
        for (int p = 0; p < 2; p++) {
            const float4 v = *(const float4*)(W + (size_t)(k0 + br + 8 * p) * DIM + (col0 + bc));
            *(float4*)(&Bs[br + 8 * p][bc]) = v;
        }
        __syncthreads();

        #pragma unroll
        for (int kk = 0; kk < BK; kk++) {
            float aF[TM], bF[TN];
            const float4 a0 = *(const float4*)(&As[kk][ty * TM + 0]);
            const float4 a1 = *(const float4*)(&As[kk][ty * TM + 4]);
            aF[0]=a0.x; aF[1]=a0.y; aF[2]=a0.z; aF[3]=a0.w;
            aF[4]=a1.x; aF[5]=a1.y; aF[6]=a1.z; aF[7]=a1.w;
            const float4 b0 = *(const float4*)(&Bs[kk][tx * TN + 0]);
            const float4 b1 = *(const float4*)(&Bs[kk][tx * TN + 4]);
            bF[0]=b0.x; bF[1]=b0.y; bF[2]=b0.z; bF[3]=b0.w;
            bF[4]=b1.x; bF[5]=b1.y; bF[6]=b1.z; bF[7]=b1.w;
            #pragma unroll
            for (int i = 0; i < TM; i++)
                #pragma unroll
                for (int j = 0; j < TN; j++)
                    acc[i][j] = fmaf(aF[i], bF[j], acc[i][j]);
        }
        __syncthreads();
    }

    // epilogue
    float bv[TN];
    #pragma unroll
    for (int j = 0; j < TN; j++) bv[j] = bias[col0 + tx * TN + j];

    #pragma unroll
    for (int i = 0; i < TM; i++) {
        const size_t rbase = (size_t)(row0 + ty * TM + i) * DIM + (col0 + tx * TN);
        float vals[TN];
        if (z == 0) {
            #pragma unroll
            for (int j = 0; j < TN; j++)
                vals[j] = 1.0f - sigmoid_fast(acc[i][j] + bv[j]);   // a = 1 - z
        } else {
            #pragma unroll
            for (int j = 0; j < TN; j++)
                vals[j] = acc[i][j] + bv[j];                         // h_tilde
        }
        float4 o0 = make_float4(vals[0], vals[1], vals[2], vals[3]);
        float4 o1 = make_float4(vals[4], vals[5], vals[6], vals[7]);
        *(float4*)(out + rbase + 0) = o0;
        *(float4*)(out + rbase + 4) = o1;
    }
}

// ---------------- chunked scan: pass 1 (chunk aggregates) ------------------------
__global__ __launch_bounds__(256) void scan_partial_kernel()
{
    const int g  = blockIdx.x * 256 + threadIdx.x;       // 0 .. 8*32*1024-1
    const int d  = g & (DIM - 1);
    const int bc = g >> 10;                              // b*NCHUNK + c
    const int c  = bc & (NCHUNK - 1);
    const int b  = bc >> 5;

    const size_t base = ((size_t)(b * SEQT + c * CHUNK_LEN)) * DIM + d;
    float A = 1.0f, Bv = 0.0f;
    #pragma unroll 8
    for (int t = 0; t < CHUNK_LEN; t++) {
        const float a  = g_pa[base + (size_t)t * DIM];
        const float ht = g_ph[base + (size_t)t * DIM];
        const float bt = (1.0f - a) * ht;                // b_t = z_t * h_tilde_t
        Bv = fmaf(a, Bv, bt);
        A *= a;
    }
    g_Ag[bc * DIM + d] = A;
    g_Bg[bc * DIM + d] = Bv;
}

// ---------------- chunked scan: pass 2 (carry across chunks) ---------------------
__global__ __launch_bounds__(256) void scan_carry_kernel()
{
    const int g = blockIdx.x * 256 + threadIdx.x;        // 0 .. 8191
    const int d = g & (DIM - 1);
    const int b = g >> 10;

    float h = 0.0f;
    #pragma unroll
    for (int c = 0; c < NCHUNK; c++) {
        const int idx = (b * NCHUNK + c) * DIM + d;
        g_cr[idx] = h;
        h = fmaf(g_Ag[idx], h, g_Bg[idx]);
    }
}

// ---------------- chunked scan: pass 3 (final h + fused Swish) -------------------
__global__ __launch_bounds__(256) void scan_final_kernel(const float* __restrict__ beta_ptr)
{
    const int g  = blockIdx.x * 256 + threadIdx.x;
    const int d  = g & (DIM - 1);
    const int bc = g >> 10;
    const int c  = bc & (NCHUNK - 1);
    const int b  = bc >> 5;

    const float beta = *beta_ptr;
    const size_t base = ((size_t)(b * SEQT + c * CHUNK_LEN)) * DIM + d;

    float h = g_cr[bc * DIM + d];
    #pragma unroll 8
    for (int t = 0; t < CHUNK_LEN; t++) {
        const size_t idx = base + (size_t)t * DIM;
        const float a  = g_pa[idx];
        const float ht = g_ph[idx];
        const float bt = (1.0f - a) * ht;
        h = fmaf(a, h, bt);
        const float s = beta * h;
        g_ph[idx] = s * sigmoid_fast(s);                 // y = swish(h); reuse g_ph
    }
}

// ---------------- LayerNorm over D ------------------------------------------------
__device__ __forceinline__ float block_sum_256(float v)
{
    __shared__ float red[8];
    #pragma unroll
    for (int o = 16; o > 0; o >>= 1) v += __shfl_xor_sync(0xffffffffu, v, o);
    if ((threadIdx.x & 31) == 0) red[threadIdx.x >> 5] = v;
    __syncthreads();
    float s = red[0] + red[1] + red[2] + red[3] + red[4] + red[5] + red[6] + red[7];
    __syncthreads();
    return s;
}

__global__ __launch_bounds__(256) void ln_kernel(
    const float* __restrict__ gamma, const float* __restrict__ beta,
    float* __restrict__ out)
{
    const int row = blockIdx.x;                          // 0 .. M_TOT-1
    const int tid = threadIdx.x;
    const float* __restrict__ y = g_ph + (size_t)row * DIM;

    const float4 v = ((const float4*)y)[tid];

    const float s   = v.x + v.y + v.z + v.w;
    const float tot = block_sum_256(s);
    const float mu  = tot * (1.0f / (float)DIM);

    const float dx = v.x - mu, dy = v.y - mu, dz = v.z - mu, dw = v.w - mu;
    const float sq  = dx * dx + dy * dy + dz * dz + dw * dw;
    const float var = block_sum_256(sq) * (1.0f / (float)DIM);
    const float rs  = rsqrtf(var + 1e-5f);

    const float4 gm = ((const float4*)gamma)[tid];
    const float4 bt = ((const float4*)beta)[tid];
    float4 o;
    o.x = dx * rs * gm.x + bt.x;
    o.y = dy * rs * gm.y + bt.y;
    o.z = dz * rs * gm.z + bt.z;
    o.w = dw * rs * gm.w + bt.w;
    ((float4*)(out + (size_t)row * DIM))[tid] = o;
}

// ---------------- launch ----------------------------------------------------------
extern "C" void kernel_launch(void* const* d_in, const int* in_sizes, int n_in,
                              void* d_out, int out_size)
{
    const float* x     = (const float*)d_in[0];
    const float* Wz    = (const float*)d_in[1];
    const float* bz    = (const float*)d_in[2];
    const float* Wh    = (const float*)d_in[3];
    const float* bh    = (const float*)d_in[4];
    const float* sbeta = (const float*)d_in[5];
    const float* gamma = (const float*)d_in[6];
    const float* lbeta = (const float*)d_in[7];
    float* out = (float*)d_out;

    // dual GEMM + fused activation epilogue
    dim3 ggrid(DIM / BN, M_TOT / BM, 2);   // (8, 128, 2)
    gemm_fused_kernel<<<ggrid, 256>>>(x, Wz, bz, Wh, bh);

    // chunked associative scan
    scan_partial_kernel<<<(BATCH * NCHUNK * DIM) / 256, 256>>>();
    scan_carry_kernel<<<(BATCH * DIM) / 256, 256>>>();
    scan_final_kernel<<<(BATCH * NCHUNK * DIM) / 256, 256>>>(sbeta);

    // layernorm
    ln_kernel<<<M_TOT, 256>>>(gamma, lbeta, out);
}

// round 3
// speedup vs baseline: 2.1283x; 2.1283x over previous
#include <cuda_runtime.h>
#include <cuda_bf16.h>
#include <math.h>
#include <stdint.h>

// ---------------- problem constants ----------------
#define BATCH 8
#define SEQT  2048
#define DIM   1024
#define M_TOT (BATCH * SEQT)          // 16384
#define NCHUNK 32
#define CHUNK_LEN (SEQT / NCHUNK)     // 64

// ---------------- scratch ----------------
__device__ float g_pa[(size_t)M_TOT * DIM];   // a = 1 - sigmoid(x Wz + bz)
__device__ float g_ph[(size_t)M_TOT * DIM];   // h_tilde ; later y = swish(h)
__device__ float g_Ag[BATCH * NCHUNK * DIM];
__device__ float g_Bg[BATCH * NCHUNK * DIM];
__device__ float g_cr[BATCH * NCHUNK * DIM];
__device__ __nv_bfloat16 g_X2[(size_t)M_TOT * 2048];   // row m: [0:1024)=hi, [1024:2048)=lo
__device__ __nv_bfloat16 g_Wt[(size_t)2048 * 2048];    // row n (0..1023 Wz^T, 1024..2047 Wh^T): hi | lo over k

// ---------------- FFMA-only fast sigmoid ----------------
__device__ __forceinline__ float sigmoid_fast(float x) {
    const float LOG2E = 1.4426950408889634f;
    float ax = fabsf(x);
    float t  = fminf(ax * LOG2E, 120.0f);
    float r  = -t;
    float n  = floorf(r);
    float f  = r - n;
    float p = 1.5403530393381609e-4f;
    p = fmaf(p, f, 1.3333558146428443e-3f);
    p = fmaf(p, f, 9.618129107628477e-3f);
    p = fmaf(p, f, 5.550410866482158e-2f);
    p = fmaf(p, f, 2.402265069591007e-1f);
    p = fmaf(p, f, 6.931471805599453e-1f);
    p = fmaf(p, f, 1.0f);
    int ni = (int)n;
    float scale = __int_as_float((ni + 127) << 23);
    float u = scale * p;
    float y  = 1.0f + u;
    float w  = fmaf(-0.5f, y, 1.4571f);
    float e;
    e = fmaf(-y, w, 1.0f); w = fmaf(w, e, w);
    e = fmaf(-y, w, 1.0f); w = fmaf(w, e, w);
    e = fmaf(-y, w, 1.0f); w = fmaf(w, e, w);
    return (x >= 0.0f) ? w : (1.0f - w);
}

// ---------------- PTX helpers (sm_80-level only; no tcgen05) ----------------
__device__ __forceinline__ uint32_t smem_u32(const void* p) {
    uint32_t a;
    asm("{ .reg .u64 t; cvta.to.shared.u64 t, %1; cvt.u32.u64 %0, t; }" : "=r"(a) : "l"(p));
    return a;
}
__device__ __forceinline__ void cp16(uint32_t dst, const void* src) {
    asm volatile("cp.async.cg.shared.global [%0], [%1], 16;" :: "r"(dst), "l"(src) : "memory");
}
__device__ __forceinline__ void ldsm4(uint32_t* r, uint32_t addr) {
    asm volatile("ldmatrix.sync.aligned.m8n8.x4.shared.b16 {%0,%1,%2,%3}, [%4];"
                 : "=r"(r[0]), "=r"(r[1]), "=r"(r[2]), "=r"(r[3]) : "r"(addr));
}
__device__ __forceinline__ void mma_bf16(float* d, const uint32_t* a, const uint32_t* b) {
    asm volatile(
        "mma.sync.aligned.m16n8k16.row.col.f32.bf16.bf16.f32 "
        "{%0,%1,%2,%3}, {%4,%5,%6,%7}, {%8,%9}, {%0,%1,%2,%3};"
        : "+f"(d[0]), "+f"(d[1]), "+f"(d[2]), "+f"(d[3])
        : "r"(a[0]), "r"(a[1]), "r"(a[2]), "r"(a[3]), "r"(b[0]), "r"(b[1]));
}

// ---------------- preprocess: X -> bf16 hi/lo ----------------
__global__ __launch_bounds__(256) void convx_kernel(const float* __restrict__ X)
{
    int t = blockIdx.x * 256 + threadIdx.x;
    int m = t >> 8;
    int g = t & 255;
    const float4 v = *(const float4*)(X + (size_t)m * 1024 + g * 4);
    __nv_bfloat16 h0 = __float2bfloat16(v.x);
    __nv_bfloat16 h1 = __float2bfloat16(v.y);
    __nv_bfloat16 h2 = __float2bfloat16(v.z);
    __nv_bfloat16 h3 = __float2bfloat16(v.w);
    __nv_bfloat16 l0 = __float2bfloat16(v.x - __bfloat162float(h0));
    __nv_bfloat16 l1 = __float2bfloat16(v.y - __bfloat162float(h1));
    __nv_bfloat16 l2 = __float2bfloat16(v.z - __bfloat162float(h2));
    __nv_bfloat16 l3 = __float2bfloat16(v.w - __bfloat162float(h3));
    __nv_bfloat16* rowp = &g_X2[(size_t)m * 2048];
    *(__nv_bfloat162*)(rowp + g * 4 + 0) = __nv_bfloat162(h0, h1);
    *(__nv_bfloat162*)(rowp + g * 4 + 2) = __nv_bfloat162(h2, h3);
    *(__nv_bfloat162*)(rowp + 1024 + g * 4 + 0) = __nv_bfloat162(l0, l1);
    *(__nv_bfloat162*)(rowp + 1024 + g * 4 + 2) = __nv_bfloat162(l2, l3);
}

// ---------------- preprocess: W transpose -> bf16 hi/lo ----------------
__global__ __launch_bounds__(256) void convw_kernel(const float* __restrict__ Wz,
                                                    const float* __restrict__ Wh)
{
    __shared__ float tile[32][33];
    const int zz = blockIdx.z;
    const float* __restrict__ W = zz ? Wh : Wz;
    const int k0 = blockIdx.x * 32;
    const int n0 = blockIdx.y * 32;
    const int tx = threadIdx.x;          // 0..31
    const int ty = threadIdx.y;          // 0..7
    #pragma unroll
    for (int i = 0; i < 4; i++)
        tile[ty + 8 * i][tx] = W[(size_t)(k0 + ty + 8 * i) * 1024 + n0 + tx];
    __syncthreads();
    #pragma unroll
    for (int i = 0; i < 4; i++) {
        const int n = n0 + ty + 8 * i;
        const float v = tile[tx][ty + 8 * i];
        const __nv_bfloat16 h = __float2bfloat16(v);
        const __nv_bfloat16 l = __float2bfloat16(v - __bfloat162float(h));
        const size_t rowb = (size_t)(zz * 1024 + n) * 2048;
        g_Wt[rowb + k0 + tx] = h;
        g_Wt[rowb + 1024 + k0 + tx] = l;
    }
}

// ---------------- HMMA dual GEMM (bf16x3, fp32 accum in regs) ----------------
// C[16384, 2048] = X2 . Wt^T  done as 3 product segments (hi*hi, lo*hi, hi*lo).
// CTA tile: 128(M) x 256(N); K-chunk 64; 48 chunks; cp.async double buffer.
#define BM 128
#define BN 256
#define NK 48
#define A_BYTES (128 * 128)            // 16 KB (128 rows x 128 B)
#define B_BYTES (256 * 128)            // 32 KB
#define STAGE_BYTES (A_BYTES + B_BYTES)  // 48 KB
#define OFF_BIAS (2 * STAGE_BYTES)       // 98304
#define GEMM_SMEM (OFF_BIAS + 1024)

__global__ __launch_bounds__(256, 1) void gemm_hmma_kernel(
    const float* __restrict__ bz, const float* __restrict__ bh)
{
    extern __shared__ char smem[];
    const uint32_t sb = smem_u32(smem);
    const int tid  = threadIdx.x;
    const int wid  = tid >> 5;
    const int lane = tid & 31;
    const int n0 = blockIdx.x * BN;   // 0..2047 (z half then h half)
    const int m0 = blockIdx.y * BM;

    const bool isZ = (n0 < 1024);
    const int ncol = n0 & 1023;

    // bias -> smem (separate region; consumed after final syncthreads)
    {
        const float* __restrict__ bias = isZ ? bz : bh;
        ((float*)(smem + OFF_BIAS))[tid] = bias[ncol + tid];
    }

    // warp tiling: 2 (M) x 4 (N) warps, 64x64 each
    const int wm = wid & 1;
    const int wn = wid >> 1;

    // ldmatrix lane addressing (within tile, stage-relative)
    // A: row = wm*64 + mt*16 + (lane&15), kbyte = ks*32 + (lane>>4)*16
    const int a_row  = wm * 64 + (lane & 15);
    const uint32_t a_xor  = (uint32_t)((a_row & 7) << 4);
    const uint32_t a_half = (uint32_t)((lane >> 4) * 16);
    // B: row = wn*64 + p*16 + ((lane>>3)&1)*8 + (lane&7), kbyte = ks*32 + (lane>>4)*16
    const int b_row  = wn * 64 + ((lane >> 3) & 1) * 8 + (lane & 7);
    const uint32_t b_xor  = (uint32_t)((b_row & 7) << 4);
    const uint32_t b_half = (uint32_t)((lane >> 4) * 16);

    float acc[4][8][4];
    #pragma unroll
    for (int i = 0; i < 4; i++)
        #pragma unroll
        for (int j = 0; j < 8; j++)
            #pragma unroll
            for (int q = 0; q < 4; q++) acc[i][j][q] = 0.0f;

    // ---- async tile loader ----
    auto load_chunk = [&](int kc) {
        const int st = kc & 1;
        const uint32_t stb = sb + st * STAGE_BYTES;
        const int seg = kc >> 4;
        const int kk  = (kc & 15) << 6;
        const int a_k0 = ((seg == 1) ? 1024 : 0) + kk;   // seg2 -> hi A
        const int b_k0 = ((seg == 2) ? 1024 : 0) + kk;   // seg1 -> hi B
        #pragma unroll
        for (int i = 0; i < 4; i++) {
            const int idx = tid + 256 * i;
            const int r = idx >> 3, g = idx & 7;
            const void* src = &g_X2[(size_t)(m0 + r) * 2048 + a_k0 + g * 8];
            cp16(stb + (uint32_t)(r * 128 + ((g * 16) ^ ((r & 7) << 4))), src);
        }
        #pragma unroll
        for (int i = 0; i < 8; i++) {
            const int idx = tid + 256 * i;
            const int r = idx >> 3, g = idx & 7;
            const void* src = &g_Wt[(size_t)(n0 + r) * 2048 + b_k0 + g * 8];
            cp16(stb + A_BYTES + (uint32_t)(r * 128 + ((g * 16) ^ ((r & 7) << 4))), src);
        }
        asm volatile("cp.async.commit_group;" ::: "memory");
    };

    load_chunk(0);

    for (int kc = 0; kc < NK; kc++) {
        if (kc + 1 < NK) {
            load_chunk(kc + 1);
            asm volatile("cp.async.wait_group 1;" ::: "memory");
        } else {
            asm volatile("cp.async.wait_group 0;" ::: "memory");
        }
        __syncthreads();

        const uint32_t stb = sb + (uint32_t)((kc & 1) * STAGE_BYTES);
        #pragma unroll
        for (int ks = 0; ks < 4; ks++) {
            uint32_t afr[4][4];
            uint32_t bfr[8][2];
            const uint32_t kbase = (uint32_t)(ks * 32);
            #pragma unroll
            for (int mt = 0; mt < 4; mt++) {
                const uint32_t addr = stb + (uint32_t)((a_row + mt * 16) * 128)
                                    + ((kbase + a_half) ^ a_xor);
                ldsm4(afr[mt], addr);
            }
            #pragma unroll
            for (int p = 0; p < 4; p++) {
                uint32_t r4[4];
                const uint32_t addr = stb + A_BYTES + (uint32_t)((b_row + p * 16) * 128)
                                    + ((kbase + b_half) ^ b_xor);
                ldsm4(r4, addr);
                bfr[2 * p + 0][0] = r4[0]; bfr[2 * p + 0][1] = r4[2];
                bfr[2 * p + 1][0] = r4[1]; bfr[2 * p + 1][1] = r4[3];
            }
            #pragma unroll
            for (int mt = 0; mt < 4; mt++)
                #pragma unroll
                for (int nt = 0; nt < 8; nt++)
                    mma_bf16(acc[mt][nt], afr[mt], bfr[nt]);
        }
        __syncthreads();
    }

    // ---- epilogue: bias + activation, direct global stores ----
    const float* sh_bias = (const float*)(smem + OFF_BIAS);
    float* __restrict__ outp = isZ ? g_pa : g_ph;
    const int quad = lane >> 2;
    const int tq   = lane & 3;

    #pragma unroll
    for (int mt = 0; mt < 4; mt++) {
        const int row = m0 + wm * 64 + mt * 16 + quad;
        #pragma unroll
        for (int nt = 0; nt < 8; nt++) {
            const int cloc = wn * 64 + nt * 8 + tq * 2;
            const float b0 = sh_bias[cloc];
            const float b1 = sh_bias[cloc + 1];
            float v0 = acc[mt][nt][0] + b0;
            float v1 = acc[mt][nt][1] + b1;
            float v2 = acc[mt][nt][2] + b0;
            float v3 = acc[mt][nt][3] + b1;
            if (isZ) {
                v0 = 1.0f - sigmoid_fast(v0);
                v1 = 1.0f - sigmoid_fast(v1);
                v2 = 1.0f - sigmoid_fast(v2);
                v3 = 1.0f - sigmoid_fast(v3);
            }
            *(float2*)(outp + (size_t)row * 1024 + ncol + cloc)       = make_float2(v0, v1);
            *(float2*)(outp + (size_t)(row + 8) * 1024 + ncol + cloc) = make_float2(v2, v3);
        }
    }
}

// ---------------- chunked scan: pass 1 ----------------
__global__ __launch_bounds__(256) void scan_partial_kernel()
{
    const int g  = blockIdx.x * 256 + threadIdx.x;
    const int d  = g & (DIM - 1);
    const int bc = g >> 10;
    const int c  = bc & (NCHUNK - 1);
    const int b  = bc >> 5;

    const size_t base = ((size_t)(b * SEQT + c * CHUNK_LEN)) * DIM + d;
    float A = 1.0f, Bv = 0.0f;
    #pragma unroll 8
    for (int t = 0; t < CHUNK_LEN; t++) {
        const float a  = g_pa[base + (size_t)t * DIM];
        const float ht = g_ph[base + (size_t)t * DIM];
        const float bt = (1.0f - a) * ht;
        Bv = fmaf(a, Bv, bt);
        A *= a;
    }
    g_Ag[bc * DIM + d] = A;
    g_Bg[bc * DIM + d] = Bv;
}

// ---------------- chunked scan: pass 2 ----------------
__global__ __launch_bounds__(256) void scan_carry_kernel()
{
    const int g = blockIdx.x * 256 + threadIdx.x;
    const int d = g & (DIM - 1);
    const int b = g >> 10;

    float h = 0.0f;
    #pragma unroll
    for (int c = 0; c < NCHUNK; c++) {
        const int idx = (b * NCHUNK + c) * DIM + d;
        g_cr[idx] = h;
        h = fmaf(g_Ag[idx], h, g_Bg[idx]);
    }
}

// ---------------- chunked scan: pass 3 + Swish ----------------
__global__ __launch_bounds__(256) void scan_final_kernel(const float* __restrict__ beta_ptr)
{
    const int g  = blockIdx.x * 256 + threadIdx.x;
    const int d  = g & (DIM - 1);
    const int bc = g >> 10;
    const int c  = bc & (NCHUNK - 1);
    const int b  = bc >> 5;

    const float beta = *beta_ptr;
    const size_t base = ((size_t)(b * SEQT + c * CHUNK_LEN)) * DIM + d;

    float h = g_cr[bc * DIM + d];
    #pragma unroll 8
    for (int t = 0; t < CHUNK_LEN; t++) {
        const size_t idx = base + (size_t)t * DIM;
        const float a  = g_pa[idx];
        const float ht = g_ph[idx];
        const float bt = (1.0f - a) * ht;
        h = fmaf(a, h, bt);
        const float s = beta * h;
        g_ph[idx] = s * sigmoid_fast(s);
    }
}

// ---------------- LayerNorm ----------------
__device__ __forceinline__ float block_sum_256(float v)
{
    __shared__ float red[8];
    #pragma unroll
    for (int o = 16; o > 0; o >>= 1) v += __shfl_xor_sync(0xffffffffu, v, o);
    if ((threadIdx.x & 31) == 0) red[threadIdx.x >> 5] = v;
    __syncthreads();
    float s = red[0] + red[1] + red[2] + red[3] + red[4] + red[5] + red[6] + red[7];
    __syncthreads();
    return s;
}

__global__ __launch_bounds__(256) void ln_kernel(
    const float* __restrict__ gamma, const float* __restrict__ beta,
    float* __restrict__ out)
{
    const int row = blockIdx.x;
    const int tid = threadIdx.x;
    const float* __restrict__ y = g_ph + (size_t)row * DIM;

    const float4 v = ((const float4*)y)[tid];
    const float s   = v.x + v.y + v.z + v.w;
    const float tot = block_sum_256(s);
    const float mu  = tot * (1.0f / (float)DIM);

    const float dx = v.x - mu, dy = v.y - mu, dz = v.z - mu, dw = v.w - mu;
    const float sq  = dx * dx + dy * dy + dz * dz + dw * dw;
    const float var = block_sum_256(sq) * (1.0f / (float)DIM);
    const float rs  = rsqrtf(var + 1e-5f);

    const float4 gm = ((const float4*)gamma)[tid];
    const float4 bt = ((const float4*)beta)[tid];
    float4 o;
    o.x = dx * rs * gm.x + bt.x;
    o.y = dy * rs * gm.y + bt.y;
    o.z = dz * rs * gm.z + bt.z;
    o.w = dw * rs * gm.w + bt.w;
    ((float4*)(out + (size_t)row * DIM))[tid] = o;
}

// ---------------- launch ----------------
extern "C" void kernel_launch(void* const* d_in, const int* in_sizes, int n_in,
                              void* d_out, int out_size)
{
    const float* x     = (const float*)d_in[0];
    const float* Wz    = (const float*)d_in[1];
    const float* bz    = (const float*)d_in[2];
    const float* Wh    = (const float*)d_in[3];
    const float* bh    = (const float*)d_in[4];
    const float* sbeta = (const float*)d_in[5];
    const float* gamma = (const float*)d_in[6];
    const float* lbeta = (const float*)d_in[7];
    float* out = (float*)d_out;

    // preprocess: fp32 -> bf16 hi/lo (X) and transposed hi/lo (W)
    convx_kernel<<<M_TOT, 256>>>(x);
    dim3 wgrid(32, 32, 2);
    convw_kernel<<<wgrid, dim3(32, 8)>>>(Wz, Wh);

    // tensor-core dual GEMM (bf16x3 via mma.sync) + fused bias/activation epilogue
    cudaFuncSetAttribute(gemm_hmma_kernel, cudaFuncAttributeMaxDynamicSharedMemorySize, GEMM_SMEM);
    gemm_hmma_kernel<<<dim3(2048 / BN, M_TOT / BM), 256, GEMM_SMEM>>>(bz, bh);

    // chunked associative scan
    scan_partial_kernel<<<(BATCH * NCHUNK * DIM) / 256, 256>>>();
    scan_carry_kernel<<<(BATCH * DIM) / 256, 256>>>();
    scan_final_kernel<<<(BATCH * NCHUNK * DIM) / 256, 256>>>(sbeta);

    // layernorm
    ln_kernel<<<M_TOT, 256>>>(gamma, lbeta, out);
}

// round 5
// speedup vs baseline: 2.1489x; 1.0097x over previous
#include <cuda_runtime.h>
#include <cuda_bf16.h>
#include <math.h>
#include <stdint.h>

// ---------------- problem constants ----------------
#define BATCH 8
#define SEQT  2048
#define DIM   1024
#define M_TOT (BATCH * SEQT)          // 16384
#define NCHUNK 32
#define CHUNK_LEN (SEQT / NCHUNK)     // 64

// ---------------- scratch ----------------
__device__ float g_pa[(size_t)M_TOT * DIM];   // a = 1 - sigmoid(x Wz + bz)
__device__ float g_ph[(size_t)M_TOT * DIM];   // h_tilde
__device__ float g_Ag[BATCH * NCHUNK * DIM];
__device__ float g_Bg[BATCH * NCHUNK * DIM];
__device__ float g_cr[BATCH * NCHUNK * DIM];
__device__ __nv_bfloat16 g_X2[(size_t)M_TOT * 2048];   // row m: [0:1024)=hi, [1024:2048)=lo
__device__ __nv_bfloat16 g_Wt[(size_t)2048 * 2048];    // row n (0..1023 Wz^T, 1024..2047 Wh^T): hi | lo

// ---------------- FFMA-only fast sigmoid ----------------
__device__ __forceinline__ float sigmoid_fast(float x) {
    const float LOG2E = 1.4426950408889634f;
    float ax = fabsf(x);
    float t  = fminf(ax * LOG2E, 120.0f);
    float r  = -t;
    float n  = floorf(r);
    float f  = r - n;
    float p = 1.5403530393381609e-4f;
    p = fmaf(p, f, 1.3333558146428443e-3f);
    p = fmaf(p, f, 9.618129107628477e-3f);
    p = fmaf(p, f, 5.550410866482158e-2f);
    p = fmaf(p, f, 2.402265069591007e-1f);
    p = fmaf(p, f, 6.931471805599453e-1f);
    p = fmaf(p, f, 1.0f);
    int ni = (int)n;
    float scale = __int_as_float((ni + 127) << 23);
    float u = scale * p;
    float y  = 1.0f + u;
    float w  = fmaf(-0.5f, y, 1.4571f);
    float e;
    e = fmaf(-y, w, 1.0f); w = fmaf(w, e, w);
    e = fmaf(-y, w, 1.0f); w = fmaf(w, e, w);
    e = fmaf(-y, w, 1.0f); w = fmaf(w, e, w);
    return (x >= 0.0f) ? w : (1.0f - w);
}

// ---------------- PTX helpers ----------------
__device__ __forceinline__ uint32_t smem_u32(const void* p) {
    uint32_t a;
    asm("{ .reg .u64 t; cvta.to.shared.u64 t, %1; cvt.u32.u64 %0, t; }" : "=r"(a) : "l"(p));
    return a;
}
__device__ __forceinline__ void cp16(uint32_t dst, const void* src) {
    asm volatile("cp.async.cg.shared.global [%0], [%1], 16;" :: "r"(dst), "l"(src) : "memory");
}
__device__ __forceinline__ void ldsm4(uint32_t* r, uint32_t addr) {
    asm volatile("ldmatrix.sync.aligned.m8n8.x4.shared.b16 {%0,%1,%2,%3}, [%4];"
                 : "=r"(r[0]), "=r"(r[1]), "=r"(r[2]), "=r"(r[3]) : "r"(addr));
}
__device__ __forceinline__ void mma_bf16(float* d, const uint32_t* a, const uint32_t* b) {
    asm volatile(
        "mma.sync.aligned.m16n8k16.row.col.f32.bf16.bf16.f32 "
        "{%0,%1,%2,%3}, {%4,%5,%6,%7}, {%8,%9}, {%0,%1,%2,%3};"
        : "+f"(d[0]), "+f"(d[1]), "+f"(d[2]), "+f"(d[3])
        : "r"(a[0]), "r"(a[1]), "r"(a[2]), "r"(a[3]), "r"(b[0]), "r"(b[1]));
}

// ---------------- preprocess: X -> bf16 hi/lo ----------------
__global__ __launch_bounds__(256) void convx_kernel(const float* __restrict__ X)
{
    int t = blockIdx.x * 256 + threadIdx.x;
    int m = t >> 8;
    int g = t & 255;
    const float4 v = *(const float4*)(X + (size_t)m * 1024 + g * 4);
    __nv_bfloat16 h0 = __float2bfloat16(v.x);
    __nv_bfloat16 h1 = __float2bfloat16(v.y);
    __nv_bfloat16 h2 = __float2bfloat16(v.z);
    __nv_bfloat16 h3 = __float2bfloat16(v.w);
    __nv_bfloat16 l0 = __float2bfloat16(v.x - __bfloat162float(h0));
    __nv_bfloat16 l1 = __float2bfloat16(v.y - __bfloat162float(h1));
    __nv_bfloat16 l2 = __float2bfloat16(v.z - __bfloat162float(h2));
    __nv_bfloat16 l3 = __float2bfloat16(v.w - __bfloat162float(h3));
    __nv_bfloat16* rowp = &g_X2[(size_t)m * 2048];
    *(__nv_bfloat162*)(rowp + g * 4 + 0) = __nv_bfloat162(h0, h1);
    *(__nv_bfloat162*)(rowp + g * 4 + 2) = __nv_bfloat162(h2, h3);
    *(__nv_bfloat162*)(rowp + 1024 + g * 4 + 0) = __nv_bfloat162(l0, l1);
    *(__nv_bfloat162*)(rowp + 1024 + g * 4 + 2) = __nv_bfloat162(l2, l3);
}

// ---------------- preprocess: W transpose -> bf16 hi/lo ----------------
__global__ __launch_bounds__(256) void convw_kernel(const float* __restrict__ Wz,
                                                    const float* __restrict__ Wh)
{
    __shared__ float tile[32][33];
    const int zz = blockIdx.z;
    const float* __restrict__ W = zz ? Wh : Wz;
    const int k0 = blockIdx.x * 32;
    const int n0 = blockIdx.y * 32;
    const int tx = threadIdx.x;
    const int ty = threadIdx.y;
    #pragma unroll
    for (int i = 0; i < 4; i++)
        tile[ty + 8 * i][tx] = W[(size_t)(k0 + ty + 8 * i) * 1024 + n0 + tx];
    __syncthreads();
    #pragma unroll
    for (int i = 0; i < 4; i++) {
        const int n = n0 + ty + 8 * i;
        const float v = tile[tx][ty + 8 * i];
        const __nv_bfloat16 h = __float2bfloat16(v);
        const __nv_bfloat16 l = __float2bfloat16(v - __bfloat162float(h));
        const size_t rowb = (size_t)(zz * 1024 + n) * 2048;
        g_Wt[rowb + k0 + tx] = h;
        g_Wt[rowb + 1024 + k0 + tx] = l;
    }
}

// ---------------- HMMA dual GEMM (bf16x3, fp32 accum), 4-stage pipeline ----------
#define BM 128
#define BN 256
#define NK 48
#define NSTAGE 4
#define A_BYTES (128 * 128)                 // 16 KB
#define B_BYTES (256 * 128)                 // 32 KB
#define STAGE_BYTES (A_BYTES + B_BYTES)     // 48 KB
#define OFF_BIAS (NSTAGE * STAGE_BYTES)     // 196608
#define GEMM_SMEM (OFF_BIAS + 1024)

__global__ __launch_bounds__(256, 1) void gemm_hmma_kernel(
    const float* __restrict__ bz, const float* __restrict__ bh)
{
    extern __shared__ char smem[];
    const uint32_t sb = smem_u32(smem);
    const int tid  = threadIdx.x;
    const int wid  = tid >> 5;
    const int lane = tid & 31;
    const int n0 = blockIdx.x * BN;
    const int m0 = blockIdx.y * BM;

    const bool isZ = (n0 < 1024);
    const int ncol = n0 & 1023;

    {
        const float* __restrict__ bias = isZ ? bz : bh;
        ((float*)(smem + OFF_BIAS))[tid] = bias[ncol + tid];
    }

    const int wm = wid & 1;
    const int wn = wid >> 1;

    const int a_row  = wm * 64 + (lane & 15);
    const uint32_t a_xor  = (uint32_t)((a_row & 7) << 4);
    const uint32_t a_half = (uint32_t)((lane >> 4) * 16);
    const int b_row  = wn * 64 + ((lane >> 3) & 1) * 8 + (lane & 7);
    const uint32_t b_xor  = (uint32_t)((b_row & 7) << 4);
    const uint32_t b_half = (uint32_t)((lane >> 4) * 16);

    float acc[4][8][4];
    #pragma unroll
    for (int i = 0; i < 4; i++)
        #pragma unroll
        for (int j = 0; j < 8; j++)
            #pragma unroll
            for (int q = 0; q < 4; q++) acc[i][j][q] = 0.0f;

    auto load_chunk = [&](int kc) {
        const uint32_t stb = sb + (uint32_t)((kc & (NSTAGE - 1)) * STAGE_BYTES);
        const int seg = kc >> 4;
        const int kk  = (kc & 15) << 6;
        const int a_k0 = ((seg == 1) ? 1024 : 0) + kk;
        const int b_k0 = ((seg == 2) ? 1024 : 0) + kk;
        #pragma unroll
        for (int i = 0; i < 4; i++) {
            const int idx = tid + 256 * i;
            const int r = idx >> 3, g = idx & 7;
            const void* src = &g_X2[(size_t)(m0 + r) * 2048 + a_k0 + g * 8];
            cp16(stb + (uint32_t)(r * 128 + ((g * 16) ^ ((r & 7) << 4))), src);
        }
        #pragma unroll
        for (int i = 0; i < 8; i++) {
            const int idx = tid + 256 * i;
            const int r = idx >> 3, g = idx & 7;
            const void* src = &g_Wt[(size_t)(n0 + r) * 2048 + b_k0 + g * 8];
            cp16(stb + A_BYTES + (uint32_t)(r * 128 + ((g * 16) ^ ((r & 7) << 4))), src);
        }
        asm volatile("cp.async.commit_group;" ::: "memory");
    };

    load_chunk(0);
    load_chunk(1);
    load_chunk(2);

    for (int kc = 0; kc < NK; kc++) {
        // ensure chunk kc landed (up to 2 newer groups may stay in flight)
        if (kc + 2 < NK)      asm volatile("cp.async.wait_group 2;" ::: "memory");
        else if (kc + 1 < NK) asm volatile("cp.async.wait_group 1;" ::: "memory");
        else                  asm volatile("cp.async.wait_group 0;" ::: "memory");
        __syncthreads();   // single barrier: data visibility + frees buf[(kc-1)%4]

        if (kc + 3 < NK) load_chunk(kc + 3);   // overlaps compute below

        const uint32_t stb = sb + (uint32_t)((kc & (NSTAGE - 1)) * STAGE_BYTES);
        #pragma unroll
        for (int ks = 0; ks < 4; ks++) {
            uint32_t afr[4][4];
            uint32_t bfr[8][2];
            const uint32_t kbase = (uint32_t)(ks * 32);
            #pragma unroll
            for (int mt = 0; mt < 4; mt++) {
                const uint32_t addr = stb + (uint32_t)((a_row + mt * 16) * 128)
                                    + ((kbase + a_half) ^ a_xor);
                ldsm4(afr[mt], addr);
            }
            #pragma unroll
            for (int p = 0; p < 4; p++) {
                uint32_t r4[4];
                const uint32_t addr = stb + A_BYTES + (uint32_t)((b_row + p * 16) * 128)
                                    + ((kbase + b_half) ^ b_xor);
                ldsm4(r4, addr);
                bfr[2 * p + 0][0] = r4[0]; bfr[2 * p + 0][1] = r4[2];
                bfr[2 * p + 1][0] = r4[1]; bfr[2 * p + 1][1] = r4[3];
            }
            #pragma unroll
            for (int mt = 0; mt < 4; mt++)
                #pragma unroll
                for (int nt = 0; nt < 8; nt++)
                    mma_bf16(acc[mt][nt], afr[mt], bfr[nt]);
        }
    }

    // epilogue: bias + activation, direct global stores
    const float* sh_bias = (const float*)(smem + OFF_BIAS);
    float* __restrict__ outp = isZ ? g_pa : g_ph;
    const int quad = lane >> 2;
    const int tq   = lane & 3;

    #pragma unroll
    for (int mt = 0; mt < 4; mt++) {
        const int row = m0 + wm * 64 + mt * 16 + quad;
        #pragma unroll
        for (int nt = 0; nt < 8; nt++) {
            const int cloc = wn * 64 + nt * 8 + tq * 2;
            const float b0 = sh_bias[cloc];
            const float b1 = sh_bias[cloc + 1];
            float v0 = acc[mt][nt][0] + b0;
            float v1 = acc[mt][nt][1] + b1;
            float v2 = acc[mt][nt][2] + b0;
            float v3 = acc[mt][nt][3] + b1;
            if (isZ) {
                v0 = 1.0f - sigmoid_fast(v0);
                v1 = 1.0f - sigmoid_fast(v1);
                v2 = 1.0f - sigmoid_fast(v2);
                v3 = 1.0f - sigmoid_fast(v3);
            }
            *(float2*)(outp + (size_t)row * 1024 + ncol + cloc)       = make_float2(v0, v1);
            *(float2*)(outp + (size_t)(row + 8) * 1024 + ncol + cloc) = make_float2(v2, v3);
        }
    }
}

// ---------------- chunked scan: pass 1 ----------------
__global__ __launch_bounds__(256) void scan_partial_kernel()
{
    const int g  = blockIdx.x * 256 + threadIdx.x;
    const int d  = g & (DIM - 1);
    const int bc = g >> 10;
    const int c  = bc & (NCHUNK - 1);
    const int b  = bc >> 5;

    const size_t base = ((size_t)(b * SEQT + c * CHUNK_LEN)) * DIM + d;
    float A = 1.0f, Bv = 0.0f;
    #pragma unroll 8
    for (int t = 0; t < CHUNK_LEN; t++) {
        const float a  = g_pa[base + (size_t)t * DIM];
        const float ht = g_ph[base + (size_t)t * DIM];
        const float bt = (1.0f - a) * ht;
        Bv = fmaf(a, Bv, bt);
        A *= a;
    }
    g_Ag[bc * DIM + d] = A;
    g_Bg[bc * DIM + d] = Bv;
}

// ---------------- chunked scan: pass 2 ----------------
__global__ __launch_bounds__(256) void scan_carry_kernel()
{
    const int g = blockIdx.x * 256 + threadIdx.x;
    const int d = g & (DIM - 1);
    const int b = g >> 10;

    float h = 0.0f;
    #pragma unroll
    for (int c = 0; c < NCHUNK; c++) {
        const int idx = (b * NCHUNK + c) * DIM + d;
        g_cr[idx] = h;
        h = fmaf(g_Ag[idx], h, g_Bg[idx]);
    }
}

// ---------------- fused scan pass 3 + Swish + LayerNorm ----------------
// one block per (b, chunk): 1024 threads, each owns one d; per-t block reduction.
__global__ __launch_bounds__(1024) void sfln_kernel(
    const float* __restrict__ beta_ptr,
    const float* __restrict__ gamma, const float* __restrict__ lbeta,
    float* __restrict__ out)
{
    __shared__ float2 red[33];          // [0..31] warp partials, [32] total

    const int d  = threadIdx.x;
    const int bc = blockIdx.x;          // 0..255
    const int c  = bc & (NCHUNK - 1);
    const int b  = bc >> 5;
    const int lane = d & 31;
    const int wrp  = d >> 5;

    const float beta = *beta_ptr;
    const float gm = gamma[d];
    const float bt = lbeta[d];

    const size_t base = ((size_t)(b * SEQT + c * CHUNK_LEN)) * DIM + d;
    float h = g_cr[bc * DIM + d];

    float a  = g_pa[base];
    float ht = g_ph[base];

    for (int t = 0; t < CHUNK_LEN; t++) {
        float a_n = 0.0f, ht_n = 0.0f;
        if (t + 1 < CHUNK_LEN) {
            a_n  = g_pa[base + (size_t)(t + 1) * DIM];
            ht_n = g_ph[base + (size_t)(t + 1) * DIM];
        }
        h = fmaf(a, h, (1.0f - a) * ht);
        const float s = beta * h;
        const float y = s * sigmoid_fast(s);

        float s1 = y, s2 = y * y;
        #pragma unroll
        for (int o = 16; o > 0; o >>= 1) {
            s1 += __shfl_xor_sync(0xffffffffu, s1, o);
            s2 += __shfl_xor_sync(0xffffffffu, s2, o);
        }
        if (lane == 0) red[wrp] = make_float2(s1, s2);
        __syncthreads();
        if (d < 32) {
            float2 v = red[lane];
            #pragma unroll
            for (int o = 16; o > 0; o >>= 1) {
                v.x += __shfl_xor_sync(0xffffffffu, v.x, o);
                v.y += __shfl_xor_sync(0xffffffffu, v.y, o);
            }
            if (lane == 0) red[32] = v;
        }
        __syncthreads();
        const float2 tot = red[32];
        const float mu  = tot.x * (1.0f / 1024.0f);
        const float var = fmaf(tot.y, 1.0f / 1024.0f, -mu * mu);
        const float rs  = rsqrtf(var + 1e-5f);
        out[base + (size_t)t * DIM] = (y - mu) * rs * gm + bt;

        a = a_n; ht = ht_n;
    }
}

// ---------------- launch ----------------
extern "C" void kernel_launch(void* const* d_in, const int* in_sizes, int n_in,
                              void* d_out, int out_size)
{
    const float* x     = (const float*)d_in[0];
    const float* Wz    = (const float*)d_in[1];
    const float* bz    = (const float*)d_in[2];
    const float* Wh    = (const float*)d_in[3];
    const float* bh    = (const float*)d_in[4];
    const float* sbeta = (const float*)d_in[5];
    const float* gamma = (const float*)d_in[6];
    const float* lbeta = (const float*)d_in[7];
    float* out = (float*)d_out;

    convx_kernel<<<M_TOT, 256>>>(x);
    dim3 wgrid(32, 32, 2);
    convw_kernel<<<wgrid, dim3(32, 8)>>>(Wz, Wh);

    cudaFuncSetAttribute(gemm_hmma_kernel, cudaFuncAttributeMaxDynamicSharedMemorySize, GEMM_SMEM);
    gemm_hmma_kernel<<<dim3(2048 / BN, M_TOT / BM), 256, GEMM_SMEM>>>(bz, bh);

    scan_partial_kernel<<<(BATCH * NCHUNK * DIM) / 256, 256>>>();
    scan_carry_kernel<<<(BATCH * DIM) / 256, 256>>>();
    sfln_kernel<<<BATCH * NCHUNK, 1024>>>(sbeta, gamma, lbeta, out);
}

// round 6
// speedup vs baseline: 4.4178x; 2.0559x over previous
#include <cuda_runtime.h>
#include <cuda_fp16.h>
#include <math.h>
#include <stdint.h>

// ---------------- problem constants ----------------
#define BATCH 8
#define SEQT  2048
#define DIM   1024
#define M_TOT (BATCH * SEQT)          // 16384
#define NCHUNK 32
#define CHUNK_LEN (SEQT / NCHUNK)     // 64

// ---------------- scratch ----------------
__device__ float g_pa[(size_t)M_TOT * DIM];   // a = 1 - sigmoid(x Wz + bz)
__device__ float g_ph[(size_t)M_TOT * DIM];   // h_tilde
__device__ float g_Ag[BATCH * NCHUNK * DIM];
__device__ float g_Bg[BATCH * NCHUNK * DIM];
__device__ float g_cr[BATCH * NCHUNK * DIM];
__device__ __half g_Xh[(size_t)M_TOT * DIM];            // fp16 X
__device__ __half g_Wt[(size_t)2048 * DIM];             // row n (0..1023 Wz^T, 1024..2047 Wh^T)

// ---------------- FFMA-only fast sigmoid ----------------
__device__ __forceinline__ float sigmoid_fast(float x) {
    const float LOG2E = 1.4426950408889634f;
    float ax = fabsf(x);
    float t  = fminf(ax * LOG2E, 120.0f);
    float r  = -t;
    float n  = floorf(r);
    float f  = r - n;
    float p = 1.5403530393381609e-4f;
    p = fmaf(p, f, 1.3333558146428443e-3f);
    p = fmaf(p, f, 9.618129107628477e-3f);
    p = fmaf(p, f, 5.550410866482158e-2f);
    p = fmaf(p, f, 2.402265069591007e-1f);
    p = fmaf(p, f, 6.931471805599453e-1f);
    p = fmaf(p, f, 1.0f);
    int ni = (int)n;
    float scale = __int_as_float((ni + 127) << 23);
    float u = scale * p;
    float y  = 1.0f + u;
    float w  = fmaf(-0.5f, y, 1.4571f);
    float e;
    e = fmaf(-y, w, 1.0f); w = fmaf(w, e, w);
    e = fmaf(-y, w, 1.0f); w = fmaf(w, e, w);
    e = fmaf(-y, w, 1.0f); w = fmaf(w, e, w);
    return (x >= 0.0f) ? w : (1.0f - w);
}

// ---------------- PTX helpers ----------------
__device__ __forceinline__ uint32_t smem_u32(const void* p) {
    uint32_t a;
    asm("{ .reg .u64 t; cvta.to.shared.u64 t, %1; cvt.u32.u64 %0, t; }" : "=r"(a) : "l"(p));
    return a;
}
__device__ __forceinline__ void cp16(uint32_t dst, const void* src) {
    asm volatile("cp.async.cg.shared.global [%0], [%1], 16;" :: "r"(dst), "l"(src) : "memory");
}
__device__ __forceinline__ void ldsm4(uint32_t* r, uint32_t addr) {
    asm volatile("ldmatrix.sync.aligned.m8n8.x4.shared.b16 {%0,%1,%2,%3}, [%4];"
                 : "=r"(r[0]), "=r"(r[1]), "=r"(r[2]), "=r"(r[3]) : "r"(addr));
}
__device__ __forceinline__ void mma_f16(float* d, const uint32_t* a, const uint32_t* b) {
    asm volatile(
        "mma.sync.aligned.m16n8k16.row.col.f32.f16.f16.f32 "
        "{%0,%1,%2,%3}, {%4,%5,%6,%7}, {%8,%9}, {%0,%1,%2,%3};"
        : "+f"(d[0]), "+f"(d[1]), "+f"(d[2]), "+f"(d[3])
        : "r"(a[0]), "r"(a[1]), "r"(a[2]), "r"(a[3]), "r"(b[0]), "r"(b[1]));
}

// ---------------- preprocess: X -> fp16 ----------------
__global__ __launch_bounds__(256) void convx_kernel(const float* __restrict__ X)
{
    const int t = blockIdx.x * 256 + threadIdx.x;      // one per 4 elems
    const float4 v = ((const float4*)X)[t];
    __half2 p0 = __floats2half2_rn(v.x, v.y);
    __half2 p1 = __floats2half2_rn(v.z, v.w);
    uint2 o;
    o.x = *(uint32_t*)&p0;
    o.y = *(uint32_t*)&p1;
    ((uint2*)g_Xh)[t] = o;
}

// ---------------- preprocess: W transpose -> fp16 ----------------
__global__ __launch_bounds__(256) void convw_kernel(const float* __restrict__ Wz,
                                                    const float* __restrict__ Wh)
{
    __shared__ float tile[32][33];
    const int zz = blockIdx.z;
    const float* __restrict__ W = zz ? Wh : Wz;
    const int k0 = blockIdx.x * 32;
    const int n0 = blockIdx.y * 32;
    const int tx = threadIdx.x;
    const int ty = threadIdx.y;
    #pragma unroll
    for (int i = 0; i < 4; i++)
        tile[ty + 8 * i][tx] = W[(size_t)(k0 + ty + 8 * i) * 1024 + n0 + tx];
    __syncthreads();
    #pragma unroll
    for (int i = 0; i < 4; i++) {
        const int n = n0 + ty + 8 * i;
        g_Wt[(size_t)(zz * 1024 + n) * 1024 + k0 + tx] = __float2half_rn(tile[tx][ty + 8 * i]);
    }
}

// ---------------- HMMA dual GEMM (fp16 in, fp32 accum), 4-stage pipeline ---------
#define BM 128
#define BN 256
#define NK 16
#define NSTAGE 4
#define A_BYTES (128 * 128)                 // 16 KB (128 rows x 64 k x 2B)
#define B_BYTES (256 * 128)                 // 32 KB
#define STAGE_BYTES (A_BYTES + B_BYTES)     // 48 KB
#define OFF_BIAS (NSTAGE * STAGE_BYTES)     // 196608
#define GEMM_SMEM (OFF_BIAS + 1024)

__global__ __launch_bounds__(256, 1) void gemm_hmma_kernel(
    const float* __restrict__ bz, const float* __restrict__ bh)
{
    extern __shared__ char smem[];
    const uint32_t sb = smem_u32(smem);
    const int tid  = threadIdx.x;
    const int wid  = tid >> 5;
    const int lane = tid & 31;
    const int n0 = blockIdx.x * BN;
    const int m0 = blockIdx.y * BM;

    const bool isZ = (n0 < 1024);
    const int ncol = n0 & 1023;

    {
        const float* __restrict__ bias = isZ ? bz : bh;
        ((float*)(smem + OFF_BIAS))[tid] = bias[ncol + tid];
    }

    const int wm = wid & 1;
    const int wn = wid >> 1;

    const int a_row  = wm * 64 + (lane & 15);
    const uint32_t a_xor  = (uint32_t)((a_row & 7) << 4);
    const uint32_t a_half = (uint32_t)((lane >> 4) * 16);
    const int b_row  = wn * 64 + ((lane >> 3) & 1) * 8 + (lane & 7);
    const uint32_t b_xor  = (uint32_t)((b_row & 7) << 4);
    const uint32_t b_half = (uint32_t)((lane >> 4) * 16);

    float acc[4][8][4];
    #pragma unroll
    for (int i = 0; i < 4; i++)
        #pragma unroll
        for (int j = 0; j < 8; j++)
            #pragma unroll
            for (int q = 0; q < 4; q++) acc[i][j][q] = 0.0f;

    auto load_chunk = [&](int kc) {
        const uint32_t stb = sb + (uint32_t)((kc & (NSTAGE - 1)) * STAGE_BYTES);
        const int k0 = kc << 6;
        #pragma unroll
        for (int i = 0; i < 4; i++) {
            const int idx = tid + 256 * i;
            const int r = idx >> 3, g = idx & 7;
            const void* src = &g_Xh[(size_t)(m0 + r) * 1024 + k0 + g * 8];
            cp16(stb + (uint32_t)(r * 128 + ((g * 16) ^ ((r & 7) << 4))), src);
        }
        #pragma unroll
        for (int i = 0; i < 8; i++) {
            const int idx = tid + 256 * i;
            const int r = idx >> 3, g = idx & 7;
            const void* src = &g_Wt[(size_t)(n0 + r) * 1024 + k0 + g * 8];
            cp16(stb + A_BYTES + (uint32_t)(r * 128 + ((g * 16) ^ ((r & 7) << 4))), src);
        }
        asm volatile("cp.async.commit_group;" ::: "memory");
    };

    load_chunk(0);
    load_chunk(1);
    load_chunk(2);

    for (int kc = 0; kc < NK; kc++) {
        if (kc + 2 < NK)      asm volatile("cp.async.wait_group 2;" ::: "memory");
        else if (kc + 1 < NK) asm volatile("cp.async.wait_group 1;" ::: "memory");
        else                  asm volatile("cp.async.wait_group 0;" ::: "memory");
        __syncthreads();

        if (kc + 3 < NK) load_chunk(kc + 3);

        const uint32_t stb = sb + (uint32_t)((kc & (NSTAGE - 1)) * STAGE_BYTES);
        #pragma unroll
        for (int ks = 0; ks < 4; ks++) {
            uint32_t afr[4][4];
            uint32_t bfr[8][2];
            const uint32_t kbase = (uint32_t)(ks * 32);
            #pragma unroll
            for (int mt = 0; mt < 4; mt++) {
                const uint32_t addr = stb + (uint32_t)((a_row + mt * 16) * 128)
                                    + ((kbase + a_half) ^ a_xor);
                ldsm4(afr[mt], addr);
            }
            #pragma unroll
            for (int p = 0; p < 4; p++) {
                uint32_t r4[4];
                const uint32_t addr = stb + A_BYTES + (uint32_t)((b_row + p * 16) * 128)
                                    + ((kbase + b_half) ^ b_xor);
                ldsm4(r4, addr);
                bfr[2 * p + 0][0] = r4[0]; bfr[2 * p + 0][1] = r4[2];
                bfr[2 * p + 1][0] = r4[1]; bfr[2 * p + 1][1] = r4[3];
            }
            #pragma unroll
            for (int mt = 0; mt < 4; mt++)
                #pragma unroll
                for (int nt = 0; nt < 8; nt++)
                    mma_f16(acc[mt][nt], afr[mt], bfr[nt]);
        }
    }

    // epilogue: bias + activation, direct global stores
    const float* sh_bias = (const float*)(smem + OFF_BIAS);
    float* __restrict__ outp = isZ ? g_pa : g_ph;
    const int quad = lane >> 2;
    const int tq   = lane & 3;

    #pragma unroll
    for (int mt = 0; mt < 4; mt++) {
        const int row = m0 + wm * 64 + mt * 16 + quad;
        #pragma unroll
        for (int nt = 0; nt < 8; nt++) {
            const int cloc = wn * 64 + nt * 8 + tq * 2;
            const float b0 = sh_bias[cloc];
            const float b1 = sh_bias[cloc + 1];
            float v0 = acc[mt][nt][0] + b0;
            float v1 = acc[mt][nt][1] + b1;
            float v2 = acc[mt][nt][2] + b0;
            float v3 = acc[mt][nt][3] + b1;
            if (isZ) {
                v0 = 1.0f - sigmoid_fast(v0);
                v1 = 1.0f - sigmoid_fast(v1);
                v2 = 1.0f - sigmoid_fast(v2);
                v3 = 1.0f - sigmoid_fast(v3);
            }
            *(float2*)(outp + (size_t)row * 1024 + ncol + cloc)       = make_float2(v0, v1);
            *(float2*)(outp + (size_t)(row + 8) * 1024 + ncol + cloc) = make_float2(v2, v3);
        }
    }
}

// ---------------- chunked scan: pass 1 ----------------
__global__ __launch_bounds__(256) void scan_partial_kernel()
{
    const int g  = blockIdx.x * 256 + threadIdx.x;
    const int d  = g & (DIM - 1);
    const int bc = g >> 10;
    const int c  = bc & (NCHUNK - 1);
    const int b  = bc >> 5;

    const size_t base = ((size_t)(b * SEQT + c * CHUNK_LEN)) * DIM + d;
    float A = 1.0f, Bv = 0.0f;
    #pragma unroll 8
    for (int t = 0; t < CHUNK_LEN; t++) {
        const float a  = g_pa[base + (size_t)t * DIM];
        const float ht = g_ph[base + (size_t)t * DIM];
        const float bt = (1.0f - a) * ht;
        Bv = fmaf(a, Bv, bt);
        A *= a;
    }
    g_Ag[bc * DIM + d] = A;
    g_Bg[bc * DIM + d] = Bv;
}

// ---------------- chunked scan: pass 2 ----------------
__global__ __launch_bounds__(256) void scan_carry_kernel()
{
    const int g = blockIdx.x * 256 + threadIdx.x;
    const int d = g & (DIM - 1);
    const int b = g >> 10;

    float h = 0.0f;
    #pragma unroll
    for (int c = 0; c < NCHUNK; c++) {
        const int idx = (b * NCHUNK + c) * DIM + d;
        g_cr[idx] = h;
        h = fmaf(g_Ag[idx], h, g_Bg[idx]);
    }
}

// ---------------- fused scan pass 3 + Swish + LayerNorm ----------------
__global__ __launch_bounds__(1024) void sfln_kernel(
    const float* __restrict__ beta_ptr,
    const float* __restrict__ gamma, const float* __restrict__ lbeta,
    float* __restrict__ out)
{
    __shared__ float2 red[33];

    const int d  = threadIdx.x;
    const int bc = blockIdx.x;
    const int c  = bc & (NCHUNK - 1);
    const int b  = bc >> 5;
    const int lane = d & 31;
    const int wrp  = d >> 5;

    const float beta = *beta_ptr;
    const float gm = gamma[d];
    const float bt = lbeta[d];

    const size_t base = ((size_t)(b * SEQT + c * CHUNK_LEN)) * DIM + d;
    float h = g_cr[bc * DIM + d];

    float a  = g_pa[base];
    float ht = g_ph[base];

    for (int t = 0; t < CHUNK_LEN; t++) {
        float a_n = 0.0f, ht_n = 0.0f;
        if (t + 1 < CHUNK_LEN) {
            a_n  = g_pa[base + (size_t)(t + 1) * DIM];
            ht_n = g_ph[base + (size_t)(t + 1) * DIM];
        }
        h = fmaf(a, h, (1.0f - a) * ht);
        const float s = beta * h;
        const float y = s * sigmoid_fast(s);

        float s1 = y, s2 = y * y;
        #pragma unroll
        for (int o = 16; o > 0; o >>= 1) {
            s1 += __shfl_xor_sync(0xffffffffu, s1, o);
            s2 += __shfl_xor_sync(0xffffffffu, s2, o);
        }
        if (lane == 0) red[wrp] = make_float2(s1, s2);
        __syncthreads();
        if (d < 32) {
            float2 v = red[lane];
            #pragma unroll
            for (int o = 16; o > 0; o >>= 1) {
                v.x += __shfl_xor_sync(0xffffffffu, v.x, o);
                v.y += __shfl_xor_sync(0xffffffffu, v.y, o);
            }
            if (lane == 0) red[32] = v;
        }
        __syncthreads();
        const float2 tot = red[32];
        const float mu  = tot.x * (1.0f / 1024.0f);
        const float var = fmaf(tot.y, 1.0f / 1024.0f, -mu * mu);
        const float rs  = rsqrtf(var + 1e-5f);
        out[base + (size_t)t * DIM] = (y - mu) * rs * gm + bt;

        a = a_n; ht = ht_n;
    }
}

// ---------------- launch ----------------
extern "C" void kernel_launch(void* const* d_in, const int* in_sizes, int n_in,
                              void* d_out, int out_size)
{
    const float* x     = (const float*)d_in[0];
    const float* Wz    = (const float*)d_in[1];
    const float* bz    = (const float*)d_in[2];
    const float* Wh    = (const float*)d_in[3];
    const float* bh    = (const float*)d_in[4];
    const float* sbeta = (const float*)d_in[5];
    const float* gamma = (const float*)d_in[6];
    const float* lbeta = (const float*)d_in[7];
    float* out = (float*)d_out;

    convx_kernel<<<(M_TOT * DIM / 4) / 256, 256>>>(x);
    dim3 wgrid(32, 32, 2);
    convw_kernel<<<wgrid, dim3(32, 8)>>>(Wz, Wh);

    cudaFuncSetAttribute(gemm_hmma_kernel, cudaFuncAttributeMaxDynamicSharedMemorySize, GEMM_SMEM);
    gemm_hmma_kernel<<<dim3(2048 / BN, M_TOT / BM), 256, GEMM_SMEM>>>(bz, bh);

    scan_partial_kernel<<<(BATCH * NCHUNK * DIM) / 256, 256>>>();
    scan_carry_kernel<<<(BATCH * DIM) / 256, 256>>>();
    sfln_kernel<<<BATCH * NCHUNK, 1024>>>(sbeta, gamma, lbeta, out);
}